// round 9
// baseline (speedup 1.0000x reference)
#include <cuda_runtime.h>
#include <math.h>

#define NIMG 8
#define CCH  3
#define HI_  512
#define WI_  512
#define HO_  2048
#define WO_  2048

// x-LUT: per (layer, out_x): {wxv0, wxv1, x0c(int bits), x1c(int bits)}
// y-LUT: per (layer, out_y): {wyv0, wyv1, row0=y0c*WI (int bits), row1=y1c*WI}
__device__ float4 g_lutx[NIMG][WO_];
__device__ float4 g_luty[NIMG][HO_];

__global__ void prep_kernel(const float* __restrict__ coor) {
    int i = blockIdx.x * blockDim.x + threadIdx.x;   // 0..2047 (both dims are 2048)
    int n = blockIdx.y;                              // layer

    float c0 = coor[n * 4 + 0];
    float c1 = coor[n * 4 + 1];
    float c2 = coor[n * 4 + 2];
    float c3 = coor[n * 4 + 3];
    float X  = (1.0f / (1.0f + expf(-c0))) * (float)WO_;
    float Y  = (1.0f / (1.0f + expf(-c1))) * (float)HO_;
    float Wb = (1.0f / (1.0f + expf(-c2))) * (float)WO_;
    float Hb = (1.0f / (1.0f + expf(-c3))) * (float)HO_;
    float a  = (float)WO_ / (Wb + 1e-8f);
    float tx = 2.0f / (float)WO_ * ((float)WO_ * 0.5f - X) * a;
    float b  = (float)HO_ / (Hb + 1e-8f);
    float ty = 2.0f / (float)HO_ * ((float)HO_ * 0.5f - Y) * b;

    // x LUT
    {
        float xsn = (2.0f * (float)i + 1.0f) / (float)WO_ - 1.0f;
        float gx  = a * xsn + tx;
        float ix  = ((gx + 1.0f) * (float)WI_ - 1.0f) * 0.5f;
        float x0f = floorf(ix);
        float wx1 = ix - x0f;
        float wx0 = 1.0f - wx1;
        int   xi0 = (int)x0f;
        int   xi1 = xi0 + 1;
        float vx0 = (xi0 >= 0 && xi0 < WI_) ? 1.0f : 0.0f;
        float vx1 = (xi1 >= 0 && xi1 < WI_) ? 1.0f : 0.0f;
        int x0c = min(max(xi0, 0), WI_ - 1);
        int x1c = min(max(xi1, 0), WI_ - 1);
        g_lutx[n][i] = make_float4(wx0 * vx0, wx1 * vx1,
                                   __int_as_float(x0c), __int_as_float(x1c));
    }
    // y LUT
    {
        float ysn = (2.0f * (float)i + 1.0f) / (float)HO_ - 1.0f;
        float gy  = b * ysn + ty;
        float iy  = ((gy + 1.0f) * (float)HI_ - 1.0f) * 0.5f;
        float y0f = floorf(iy);
        float wy1 = iy - y0f;
        float wy0 = 1.0f - wy1;
        int   yi0 = (int)y0f;
        int   yi1 = yi0 + 1;
        float vy0 = (yi0 >= 0 && yi0 < HI_) ? 1.0f : 0.0f;
        float vy1 = (yi1 >= 0 && yi1 < HI_) ? 1.0f : 0.0f;
        int y0c = min(max(yi0, 0), HI_ - 1);
        int y1c = min(max(yi1, 0), HI_ - 1);
        g_luty[n][i] = make_float4(wy0 * vy0, wy1 * vy1,
                                   __int_as_float(y0c * WI_), __int_as_float(y1c * WI_));
    }
}

// Front-to-back compositing with transmittance culling.
// Block = 256 consecutive x-positions of TWO adjacent output rows; thread t
// owns pixel (xbase+t) in both rows. Small per-thread state -> high occupancy;
// x-LUT load and index math amortize over 2 rows x 3 channels.
__global__ __launch_bounds__(256) void composite_kernel(
    const float* __restrict__ src,   // [8,3,512,512]
    const float* __restrict__ bg,    // [1,3,2048,2048]
    float* __restrict__ out)         // [1,3,2048,2048]
{
    int y0 = blockIdx.y << 1;                     // rows y0, y0+1
    int x  = (blockIdx.x << 8) + threadIdx.x;     // 256 px per block

    const int plane = HO_ * WO_;
    int off0 = y0 * WO_ + x;                      // row 0
    int off1 = off0 + WO_;                        // row 1

    float C[2][3] = {{0.f,0.f,0.f},{0.f,0.f,0.f}};
    float T0 = 1.0f, T1 = 1.0f;

#pragma unroll
    for (int n = NIMG - 1; n >= 0; --n) {         // front-to-back
        if (__all_sync(0xffffffffu, (T0 + T1) == 0.0f)) break;

        float4 lyA = __ldg(&g_luty[n][y0]);       // uniform across block
        float4 lyB = __ldg(&g_luty[n][y0 + 1]);
        float swA = lyA.x + lyA.y;
        float swB = lyB.x + lyB.y;
        if (swA == 0.0f && swB == 0.0f) continue; // uniform skip

        float4 lx = __ldg(&g_lutx[n][x]);         // fully coalesced
        float wxv0 = lx.x, wxv1 = lx.y;
        float sumwx = wxv0 + wxv1;
        if (sumwx == 0.0f) continue;

        int x0c = __float_as_int(lx.z);
        int x1c = __float_as_int(lx.w);
        const float* s0 = src + (size_t)n * (CCH * HI_ * WI_);

        if (swA != 0.0f && T0 != 0.0f) {
            float m = swA * sumwx;
            float f = T0 * m;
            int i00 = __float_as_int(lyA.z) + x0c;
            int i10 = __float_as_int(lyA.w) + x0c;
            int i01 = __float_as_int(lyA.z) + x1c;
            int i11 = __float_as_int(lyA.w) + x1c;
#pragma unroll
            for (int c = 0; c < CCH; ++c) {
                const float* sp = s0 + c * (HI_ * WI_);
                float v00 = __ldg(sp + i00);
                float v10 = __ldg(sp + i10);
                float v01 = __ldg(sp + i01);
                float v11 = __ldg(sp + i11);
                float r0 = v00 * lyA.x + v10 * lyA.y;
                float r1 = v01 * lyA.x + v11 * lyA.y;
                float samp = r0 * wxv0 + r1 * wxv1;
                C[0][c] = fmaf(f, samp, C[0][c]);
            }
            T0 *= (1.0f - m);
        }
        if (swB != 0.0f && T1 != 0.0f) {
            float m = swB * sumwx;
            float f = T1 * m;
            int i00 = __float_as_int(lyB.z) + x0c;
            int i10 = __float_as_int(lyB.w) + x0c;
            int i01 = __float_as_int(lyB.z) + x1c;
            int i11 = __float_as_int(lyB.w) + x1c;
#pragma unroll
            for (int c = 0; c < CCH; ++c) {
                const float* sp = s0 + c * (HI_ * WI_);
                float v00 = __ldg(sp + i00);
                float v10 = __ldg(sp + i10);
                float v01 = __ldg(sp + i01);
                float v11 = __ldg(sp + i11);
                float r0 = v00 * lyB.x + v10 * lyB.y;
                float r1 = v01 * lyB.x + v11 * lyB.y;
                float samp = r0 * wxv0 + r1 * wxv1;
                C[1][c] = fmaf(f, samp, C[1][c]);
            }
            T1 *= (1.0f - m);
        }
    }

    // out = C + T*bg; load bg only where transmittance remains
#pragma unroll
    for (int c = 0; c < CCH; ++c) {
        float o0 = C[0][c];
        float o1 = C[1][c];
        if (T0 != 0.0f) o0 = fmaf(T0, __ldg(bg + c * plane + off0), o0);
        if (T1 != 0.0f) o1 = fmaf(T1, __ldg(bg + c * plane + off1), o1);
        out[c * plane + off0] = o0;
        out[c * plane + off1] = o1;
    }
}

extern "C" void kernel_launch(void* const* d_in, const int* in_sizes, int n_in,
                              void* d_out, int out_size) {
    const float* src  = (const float*)d_in[0];   // src_img [8,3,512,512]
    const float* bg   = (const float*)d_in[1];   // bg_img  [1,3,2048,2048]
    const float* coor = (const float*)d_in[2];   // coor    [8,4]
    float*       out  = (float*)d_out;           // [1,3,2048,2048]

    // LUT prep: 2048 indices × 8 layers
    prep_kernel<<<dim3(WO_ / 256, NIMG, 1), 256>>>(coor);

    // Composite: 8 blocks of 256 threads per row-pair; 1024 row-pairs
    dim3 grid(WO_ / 256, HO_ / 2, 1);
    composite_kernel<<<grid, 256>>>(src, bg, out);
}

// round 10
// speedup vs baseline: 1.1979x; 1.1979x over previous
#include <cuda_runtime.h>
#include <math.h>

#define NIMG 8
#define CCH  3
#define HI_  512
#define WI_  512
#define HO_  2048
#define WO_  2048

// x-LUT: per (layer, out_x): {wxv0, wxv1, x0c(int bits), x1c(int bits)}
// y-LUT: per (layer, out_y): {wyv0, wyv1, row0=y0c*WI (int bits), row1=y1c*WI}
__device__ float4 g_lutx[NIMG][WO_];
__device__ float4 g_luty[NIMG][HO_];

__global__ void prep_kernel(const float* __restrict__ coor) {
    int i = blockIdx.x * blockDim.x + threadIdx.x;   // 0..2047 (both dims are 2048)
    int n = blockIdx.y;                              // layer

    float c0 = coor[n * 4 + 0];
    float c1 = coor[n * 4 + 1];
    float c2 = coor[n * 4 + 2];
    float c3 = coor[n * 4 + 3];
    float X  = (1.0f / (1.0f + expf(-c0))) * (float)WO_;
    float Y  = (1.0f / (1.0f + expf(-c1))) * (float)HO_;
    float Wb = (1.0f / (1.0f + expf(-c2))) * (float)WO_;
    float Hb = (1.0f / (1.0f + expf(-c3))) * (float)HO_;
    float a  = (float)WO_ / (Wb + 1e-8f);
    float tx = 2.0f / (float)WO_ * ((float)WO_ * 0.5f - X) * a;
    float b  = (float)HO_ / (Hb + 1e-8f);
    float ty = 2.0f / (float)HO_ * ((float)HO_ * 0.5f - Y) * b;

    // x LUT
    {
        float xsn = (2.0f * (float)i + 1.0f) / (float)WO_ - 1.0f;
        float gx  = a * xsn + tx;
        float ix  = ((gx + 1.0f) * (float)WI_ - 1.0f) * 0.5f;
        float x0f = floorf(ix);
        float wx1 = ix - x0f;
        float wx0 = 1.0f - wx1;
        int   xi0 = (int)x0f;
        int   xi1 = xi0 + 1;
        float vx0 = (xi0 >= 0 && xi0 < WI_) ? 1.0f : 0.0f;
        float vx1 = (xi1 >= 0 && xi1 < WI_) ? 1.0f : 0.0f;
        int x0c = min(max(xi0, 0), WI_ - 1);
        int x1c = min(max(xi1, 0), WI_ - 1);
        g_lutx[n][i] = make_float4(wx0 * vx0, wx1 * vx1,
                                   __int_as_float(x0c), __int_as_float(x1c));
    }
    // y LUT
    {
        float ysn = (2.0f * (float)i + 1.0f) / (float)HO_ - 1.0f;
        float gy  = b * ysn + ty;
        float iy  = ((gy + 1.0f) * (float)HI_ - 1.0f) * 0.5f;
        float y0f = floorf(iy);
        float wy1 = iy - y0f;
        float wy0 = 1.0f - wy1;
        int   yi0 = (int)y0f;
        int   yi1 = yi0 + 1;
        float vy0 = (yi0 >= 0 && yi0 < HI_) ? 1.0f : 0.0f;
        float vy1 = (yi1 >= 0 && yi1 < HI_) ? 1.0f : 0.0f;
        int y0c = min(max(yi0, 0), HI_ - 1);
        int y1c = min(max(yi1, 0), HI_ - 1);
        g_luty[n][i] = make_float4(wy0 * vy0, wy1 * vy1,
                                   __int_as_float(y0c * WI_), __int_as_float(y1c * WI_));
    }
}

// Front-to-back compositing with transmittance culling (R8 mapping: 2 rows x
// 2 x-chunks per thread) + launch_bounds cap for 5 blocks/SM + hoisted lx loads.
__global__ __launch_bounds__(256, 5) void composite_kernel(
    const float* __restrict__ src,   // [8,3,512,512]
    const float* __restrict__ bg,    // [1,3,2048,2048]
    float* __restrict__ out)         // [1,3,2048,2048]
{
    int y0    = blockIdx.y << 1;                  // rows y0, y0+1
    int xbase = blockIdx.x << 9;                  // 512 px per block
    int t     = threadIdx.x;

    const int plane = HO_ * WO_;
    int off0 = y0 * WO_ + xbase + t;              // row 0, chunk k at off0 + 256k
    int off1 = off0 + WO_;                        // row 1

    float C[2][3][2];                             // premultiplied color accum
    float T[2][2];                                // transmittance per pixel
#pragma unroll
    for (int r = 0; r < 2; ++r)
#pragma unroll
        for (int k = 0; k < 2; ++k) {
            T[r][k] = 1.0f;
#pragma unroll
            for (int c = 0; c < CCH; ++c) C[r][c][k] = 0.0f;
        }

#pragma unroll
    for (int n = NIMG - 1; n >= 0; --n) {         // front-to-back
        float tsum = T[0][0] + T[0][1] + T[1][0] + T[1][1];
        if (__all_sync(0xffffffffu, tsum == 0.0f)) break;

        float4 lyA = __ldg(&g_luty[n][y0]);       // uniform across block
        float4 lyB = __ldg(&g_luty[n][y0 + 1]);
        float swA = lyA.x + lyA.y;
        float swB = lyB.x + lyB.y;
        if (swA == 0.0f && swB == 0.0f) continue; // uniform skip

        // hoist both x-LUT loads — back-to-back LDG.128, wide MLP window
        float4 lx0 = __ldg(&g_lutx[n][xbase + t]);
        float4 lx1 = __ldg(&g_lutx[n][xbase + t + 256]);

        int rA0 = __float_as_int(lyA.z);
        int rA1 = __float_as_int(lyA.w);
        int rB0 = __float_as_int(lyB.z);
        int rB1 = __float_as_int(lyB.w);
        const float* s0 = src + (size_t)n * (CCH * HI_ * WI_);

#pragma unroll
        for (int k = 0; k < 2; ++k) {
            float4 lx = (k == 0) ? lx0 : lx1;
            float wxv0 = lx.x, wxv1 = lx.y;
            float sumwx = wxv0 + wxv1;
            if (sumwx == 0.0f) continue;

            int x0c = __float_as_int(lx.z);
            int x1c = __float_as_int(lx.w);

            if (swA != 0.0f && T[0][k] != 0.0f) {
                float m = swA * sumwx;
                float f = T[0][k] * m;
                int i00 = rA0 + x0c, i10 = rA1 + x0c;
                int i01 = rA0 + x1c, i11 = rA1 + x1c;
#pragma unroll
                for (int c = 0; c < CCH; ++c) {
                    const float* sp = s0 + c * (HI_ * WI_);
                    float v00 = __ldg(sp + i00);
                    float v10 = __ldg(sp + i10);
                    float v01 = __ldg(sp + i01);
                    float v11 = __ldg(sp + i11);
                    float r0 = v00 * lyA.x + v10 * lyA.y;
                    float r1 = v01 * lyA.x + v11 * lyA.y;
                    float samp = r0 * wxv0 + r1 * wxv1;
                    C[0][c][k] = fmaf(f, samp, C[0][c][k]);
                }
                T[0][k] *= (1.0f - m);
            }
            if (swB != 0.0f && T[1][k] != 0.0f) {
                float m = swB * sumwx;
                float f = T[1][k] * m;
                int i00 = rB0 + x0c, i10 = rB1 + x0c;
                int i01 = rB0 + x1c, i11 = rB1 + x1c;
#pragma unroll
                for (int c = 0; c < CCH; ++c) {
                    const float* sp = s0 + c * (HI_ * WI_);
                    float v00 = __ldg(sp + i00);
                    float v10 = __ldg(sp + i10);
                    float v01 = __ldg(sp + i01);
                    float v11 = __ldg(sp + i11);
                    float r0 = v00 * lyB.x + v10 * lyB.y;
                    float r1 = v01 * lyB.x + v11 * lyB.y;
                    float samp = r0 * wxv0 + r1 * wxv1;
                    C[1][c][k] = fmaf(f, samp, C[1][c][k]);
                }
                T[1][k] *= (1.0f - m);
            }
        }
    }

    // out = C + T*bg; load bg only where transmittance remains
#pragma unroll
    for (int k = 0; k < 2; ++k) {
#pragma unroll
        for (int c = 0; c < CCH; ++c) {
            float o0 = C[0][c][k];
            float o1 = C[1][c][k];
            if (T[0][k] != 0.0f)
                o0 = fmaf(T[0][k], __ldg(bg + c * plane + off0 + (k << 8)), o0);
            if (T[1][k] != 0.0f)
                o1 = fmaf(T[1][k], __ldg(bg + c * plane + off1 + (k << 8)), o1);
            out[c * plane + off0 + (k << 8)] = o0;
            out[c * plane + off1 + (k << 8)] = o1;
        }
    }
}

extern "C" void kernel_launch(void* const* d_in, const int* in_sizes, int n_in,
                              void* d_out, int out_size) {
    const float* src  = (const float*)d_in[0];   // src_img [8,3,512,512]
    const float* bg   = (const float*)d_in[1];   // bg_img  [1,3,2048,2048]
    const float* coor = (const float*)d_in[2];   // coor    [8,4]
    float*       out  = (float*)d_out;           // [1,3,2048,2048]

    // LUT prep: 2048 indices × 8 layers
    prep_kernel<<<dim3(WO_ / 256, NIMG, 1), 256>>>(coor);

    // Composite: 4 blocks of 256 threads per row-pair; 1024 row-pairs
    dim3 grid(WO_ / 512, HO_ / 2, 1);
    composite_kernel<<<grid, 256>>>(src, bg, out);
}